// round 7
// baseline (speedup 1.0000x reference)
#include <cuda_runtime.h>
#include <cstdint>

#define T_STEPS 50
#define BATCH   1024
#define NIN     784
#define HID     256
#define NL      10
#define NROWS   (T_STEPS * BATCH)   // 51200

// scratch (static device arrays; no runtime allocation)
__device__ float g_wiT[NIN * HID];      // WiT[k][h] = Wi[h][k]
__device__ float g_wrT[HID * HID];      // WrT[k][h] = Wr[h][k]
__device__ float g_xw[NROWS * HID];     // XW[t*B+b][h], split-K-8 rounding

typedef unsigned long long ull;

// ---------------- packed f32x2 helpers (2 independent IEEE-rn fp32 lanes) ---
__device__ __forceinline__ ull f2_add(ull a, ull b) {
    ull r; asm("add.rn.f32x2 %0, %1, %2;" : "=l"(r) : "l"(a), "l"(b)); return r;
}
__device__ __forceinline__ ull f2_fma(ull a, ull b, ull c) {
    ull r; asm("fma.rn.f32x2 %0, %1, %2, %3;" : "=l"(r) : "l"(a), "l"(b), "l"(c)); return r;
}

// ---------------------------------------------------------------------------
// K0: build WiT and WrT
// ---------------------------------------------------------------------------
__global__ void k0_prep(const float* __restrict__ Wi, const float* __restrict__ Wr) {
    int idx = blockIdx.x * 256 + threadIdx.x;
    if (idx < NIN * HID) {
        int k = idx >> 8;
        int h = idx & 255;
        g_wiT[idx] = Wi[h * NIN + k];
    }
    if (idx < HID * HID) {
        int k = idx >> 8;
        int h = idx & 255;
        g_wrT[idx] = Wr[h * HID + k];
    }
}

// ---------------------------------------------------------------------------
// K1 (dense, order-exact): XW[r][h] = split-K=8 over chunks of 98 k.
// Within a chunk, ascending k, p = fma(x_k, w_k, p):
//   x=1 -> fl(p + w)  (product exact, identical to sparse in-order add)
//   x=0 -> p          (+0 identity; p never becomes -0 under RN)
// Chunk partials combined ascending (tot += p at odd half-stage ends).
// 256 threads = 8 warps; warp owns 8 rows x 256 h; lane owns h=lane*8..+7.
// Weights streamed in 49-k half-chunks, cp.async double-buffered.
// ---------------------------------------------------------------------------
#define K1T 256
#define KH 49                        // k per half-stage (2 halves = one 98-chunk)
#define NSTAGES 16                   // 784 / 49
#define W_HALF (KH * HID)            // 12544 floats
#define X_HALF (64 * KH)             // 3136 floats
#define K1_SMEM ((2 * W_HALF + 2 * X_HALF) * 4)   // 125440 bytes

__device__ __forceinline__ void k1_issue_stage(const float* __restrict__ x,
                                               float* w_s, float* x_s,
                                               int s, int ctaRow, int tid) {
    // w half-chunk: 49*256 floats contiguous in g_wiT
    const float4* wg = (const float4*)(g_wiT + (size_t)s * W_HALF);
    uint32_t wsm = (uint32_t)__cvta_generic_to_shared(w_s);
#pragma unroll
    for (int i = 0; i < 13; ++i) {                 // ceil(3136/256)
        int idx = tid + i * K1T;
        if (idx < W_HALF / 4)
            asm volatile("cp.async.cg.shared.global [%0], [%1], 16;"
                         :: "r"(wsm + idx * 16), "l"(wg + idx));
    }
    // x slice: 64 rows x 49 floats; 4 threads per row, 13 floats each
    int row = tid >> 2, seg = tid & 3;
    const float* xg = x + (size_t)(ctaRow + row) * NIN + s * KH;
    uint32_t xsm = (uint32_t)__cvta_generic_to_shared(x_s + row * KH);
#pragma unroll
    for (int i = 0; i < 13; ++i) {
        int kk = seg * 13 + i;
        if (kk < KH)
            asm volatile("cp.async.ca.shared.global [%0], [%1], 4;"
                         :: "r"(xsm + kk * 4), "l"(xg + kk));
    }
    asm volatile("cp.async.commit_group;");
}

__global__ __launch_bounds__(K1T) void k1_dense(const float* __restrict__ x) {
    extern __shared__ float k1smem[];
    float* wbuf[2] = { k1smem, k1smem + W_HALF };
    float* xbuf[2] = { k1smem + 2 * W_HALF, k1smem + 2 * W_HALF + X_HALF };

    const int tid  = threadIdx.x;
    const int lane = tid & 31;
    const int wrp  = tid >> 5;
    const int ctaRow = blockIdx.x * 64;
    const int wr0  = wrp * 8;              // warp's first row within CTA

    ull p[8][4], tot[8][4];
#pragma unroll
    for (int r = 0; r < 8; ++r)
#pragma unroll
        for (int j = 0; j < 4; ++j) { p[r][j] = 0ULL; tot[r][j] = 0ULL; }

    k1_issue_stage(x, wbuf[0], xbuf[0], 0, ctaRow, tid);

    for (int s = 0; s < NSTAGES; ++s) {
        if (s + 1 < NSTAGES) {
            k1_issue_stage(x, wbuf[(s + 1) & 1], xbuf[(s + 1) & 1], s + 1, ctaRow, tid);
            asm volatile("cp.async.wait_group 1;");
        } else {
            asm volatile("cp.async.wait_group 0;");
        }
        __syncthreads();

        const float* ws = wbuf[s & 1];
        const float* xs = xbuf[s & 1];
#pragma unroll 7
        for (int kk = 0; kk < KH; ++kk) {
            ulonglong2 wa = *(const ulonglong2*)&ws[kk * HID + lane * 8];
            ulonglong2 wb = *(const ulonglong2*)&ws[kk * HID + lane * 8 + 4];
#pragma unroll
            for (int r = 0; r < 8; ++r) {
                uint32_t xu = __float_as_uint(xs[(wr0 + r) * KH + kk]);
                ull xd; asm("mov.b64 %0, {%1, %1};" : "=l"(xd) : "r"(xu));
                p[r][0] = f2_fma(xd, wa.x, p[r][0]);
                p[r][1] = f2_fma(xd, wa.y, p[r][1]);
                p[r][2] = f2_fma(xd, wb.x, p[r][2]);
                p[r][3] = f2_fma(xd, wb.y, p[r][3]);
            }
        }
        if (s & 1) {                       // 98-chunk boundary: ascending combine
#pragma unroll
            for (int r = 0; r < 8; ++r)
#pragma unroll
                for (int j = 0; j < 4; ++j) {
                    tot[r][j] = f2_add(tot[r][j], p[r][j]);
                    p[r][j] = 0ULL;
                }
        }
        __syncthreads();                   // protect buf before next issue
    }

#pragma unroll
    for (int r = 0; r < 8; ++r) {
        float* o = g_xw + (size_t)(ctaRow + wr0 + r) * HID + lane * 8;
        *(ulonglong2*)o       = make_ulonglong2(tot[r][0], tot[r][1]);
        *(ulonglong2*)(o + 4) = make_ulonglong2(tot[r][2], tot[r][3]);
    }
}

// ---------------------------------------------------------------------------
// LIF elementwise update, separately rounded fp32 ops (matches reference HLO)
// ---------------------------------------------------------------------------
__device__ __forceinline__ void lif_lane(float& v, float& i, float xw, float rec,
                                         unsigned& z) {
    float vd = __fadd_rn(v, __fmul_rn(0.05f, __fadd_rn(__fsub_rn(0.0f, v), i)));
    float id = __fmul_rn(i, 0.9f);
    z = vd > 0.5f;
    v = z ? 0.0f : vd;
    i = __fadd_rn(__fadd_rn(id, xw), rec);
}

// ---------------------------------------------------------------------------
// K2: persistent LIF recurrence. CTA owns 4 batch rows for all 50 steps.
// Recurrent drive = split-K=8 sum over WrT rows selected by the PREVIOUS
// step's spike bitmask (in-order within each 32-wide word, words ascending).
// g_xw is streamed with .cs so WrT stays L1-resident. Readout deferred.
// ---------------------------------------------------------------------------
#define K2_ROWS 4
#define K2_THREADS 128

__global__ __launch_bounds__(K2_THREADS) void k2_steps(const float* __restrict__ Wout,
                                                       const float* __restrict__ bout,
                                                       float* __restrict__ out) {
    __shared__ uint32_t s_hist[T_STEPS][K2_ROWS][8];
    __shared__ uint8_t  s_nib[K2_ROWS][64];
    __shared__ float    s_part[K2_ROWS * NL][3];

    const int tid = threadIdx.x;
    const int q   = tid & 63;
    const int p   = tid >> 6;            // 0..1
    const int b0  = blockIdx.x * K2_ROWS;

    float4 v[2], cu[2];
    v[0]  = make_float4(0.f, 0.f, 0.f, 0.f);
    v[1]  = v[0];
    cu[0] = v[0];
    cu[1] = v[0];

    for (int t = 0; t < T_STEPS; ++t) {
#pragma unroll
        for (int rr = 0; rr < 2; ++rr) {
            const int r = p + rr * 2;    // rows p, p+2
            const float4 xwv = __ldcs(
                (const float4*)&g_xw[((size_t)(t * BATCH + b0 + r) * HID) + q * 4]);

            // recurrent drive: split-K over 8 words of 32 spikes each
            ull rec0 = 0, rec1 = 0;
            if (t > 0) {
                const uint32_t* mrow = s_hist[t - 1][r];
#pragma unroll
                for (int w8 = 0; w8 < 8; ++w8) {
                    uint32_t m = mrow[w8];
                    ull pw0 = 0, pw1 = 0;            // word partial
                    while (m) {
                        int bpos = __ffs(m) - 1;
                        m &= m - 1;
                        ulonglong2 wr =
                            *(const ulonglong2*)&g_wrT[(w8 * 32 + bpos) * HID + q * 4];
                        pw0 = f2_add(pw0, wr.x);
                        pw1 = f2_add(pw1, wr.y);
                    }
                    rec0 = f2_add(rec0, pw0);        // ascending combine
                    rec1 = f2_add(rec1, pw1);
                }
            }
            float2 ra = *(float2*)&rec0;
            float2 rb = *(float2*)&rec1;

            unsigned zx, zy, zz, zw;
            lif_lane(v[rr].x, cu[rr].x, xwv.x, ra.x, zx);
            lif_lane(v[rr].y, cu[rr].y, xwv.y, ra.y, zy);
            lif_lane(v[rr].z, cu[rr].z, xwv.z, rb.x, zz);
            lif_lane(v[rr].w, cu[rr].w, xwv.w, rb.y, zw);
            s_nib[r][q] = (uint8_t)(zx | (zy << 1) | (zz << 2) | (zw << 3));
        }

        __syncthreads();
        if (tid < 32) {
            int r = tid >> 3, w = tid & 7;
            uint32_t word = 0;
#pragma unroll
            for (int j = 0; j < 8; ++j)
                word |= (uint32_t)s_nib[r][w * 8 + j] << (4 * j);
            s_hist[t][r][w] = word;
        }
        __syncthreads();
    }

    // deferred readout (no feedback; ordering perturbs only ~1e-7 relative)
    if (tid < K2_ROWS * NL * 3) {                 // 120 threads
        int pair = tid / 3, seg = tid - pair * 3;
        int g = pair / NL, l = pair - g * NL;
        int t0 = seg * 17;
        int t1 = (seg == 2) ? T_STEPS : t0 + 17;
        float s = 0.0f;
        for (int t = t0; t < t1; ++t) {
#pragma unroll
            for (int w8 = 0; w8 < 8; ++w8) {
                uint32_t m = s_hist[t][g][w8];
                while (m) {
                    int bpos = __ffs(m) - 1;
                    m &= m - 1;
                    s = __fadd_rn(s, Wout[l * HID + w8 * 32 + bpos]);
                }
            }
        }
        s_part[pair][seg] = s;
    }
    __syncthreads();
    if (tid < K2_ROWS * NL) {                     // 40 threads
        int g = tid / NL, l = tid - (tid / NL) * NL;
        float a = __fadd_rn(__fadd_rn(s_part[tid][0], s_part[tid][1]), s_part[tid][2]);
        float val = __fdiv_rn(__fadd_rn(a, __fmul_rn((float)T_STEPS, bout[l])),
                              (float)T_STEPS);
        out[(b0 + g) * NL + l] = val;
    }
}

// ---------------------------------------------------------------------------
extern "C" void kernel_launch(void* const* d_in, const int* in_sizes, int n_in,
                              void* d_out, int out_size) {
    const float* x    = (const float*)d_in[0];
    const float* Wi   = (const float*)d_in[1];
    const float* Wr   = (const float*)d_in[2];
    const float* Wout = (const float*)d_in[3];
    const float* bout = (const float*)d_in[4];
    float* out = (float*)d_out;

    k0_prep<<<(NIN * HID + 255) / 256, 256>>>(Wi, Wr);

    static bool attr_set = false;
    if (!attr_set) {
        cudaFuncSetAttribute(k1_dense, cudaFuncAttributeMaxDynamicSharedMemorySize,
                             K1_SMEM);
        attr_set = true;
    }
    k1_dense<<<NROWS / 64, K1T, K1_SMEM>>>(x);

    k2_steps<<<BATCH / K2_ROWS, K2_THREADS>>>(Wout, bout, out);
}

// round 8
// speedup vs baseline: 1.0820x; 1.0820x over previous
#include <cuda_runtime.h>
#include <cstdint>

#define T_STEPS 50
#define BATCH   1024
#define NIN     784
#define HID     256
#define NL      10
#define NROWS   (T_STEPS * BATCH)   // 51200

// scratch (static device arrays; no runtime allocation)
__device__ float g_wiT[NIN * HID];      // WiT[k][h] = Wi[h][k]
__device__ float g_wrT[HID * HID];      // WrT[k][h] = Wr[h][k]
__device__ float g_xw[NROWS * HID];     // XW[t*B+b][h], split-K-8 rounding

typedef unsigned long long ull;

// ---------------- packed f32x2 helpers (2 independent IEEE-rn fp32 lanes) ---
__device__ __forceinline__ ull f2_add(ull a, ull b) {
    ull r; asm("add.rn.f32x2 %0, %1, %2;" : "=l"(r) : "l"(a), "l"(b)); return r;
}
__device__ __forceinline__ ull f2_fma(ull a, ull b, ull c) {
    ull r; asm("fma.rn.f32x2 %0, %1, %2, %3;" : "=l"(r) : "l"(a), "l"(b), "l"(c)); return r;
}

// ---------------------------------------------------------------------------
// K0: build WiT and WrT
// ---------------------------------------------------------------------------
__global__ void k0_prep(const float* __restrict__ Wi, const float* __restrict__ Wr) {
    int idx = blockIdx.x * 256 + threadIdx.x;
    if (idx < NIN * HID) {
        int k = idx >> 8;
        int h = idx & 255;
        g_wiT[idx] = Wi[h * NIN + k];
    }
    if (idx < HID * HID) {
        int k = idx >> 8;
        int h = idx & 255;
        g_wrT[idx] = Wr[h * HID + k];
    }
}

// ---------------------------------------------------------------------------
// K1 (union-scan, order-exact): XW[r][h] = split-K=8 sum over {k: x[r][k]=1}
// of WiT[k][h]; 8 chunks of 98, in-order within a chunk, chunks combined
// ascending. A warp owns 4 rows; per 32-k window it scans the UNION of the
// 4 rows' spike masks, loading each selected weight row once (2x LDS.128)
// and applying p_r = fma(x_r, w, p_r) per row:
//   x=1 -> fl(p+w) (exact product)   x=0 -> p (+0 identity; p never -0)
// => bit-identical to the per-row in-order sparse sequence, 37% less
// crossbar traffic (union density 76% vs 4x30%).
// WiT chunks (98x256 fp32 = 100352 B) double-buffered via cp.async.
// ---------------------------------------------------------------------------
#define K1_THREADS 512
#define RPW 4                        // rows per warp
#define RPC 64                       // rows per CTA (16 warps * 4)
#define KCHUNK 98
#define NCHUNK 8
#define CHUNK_F4 (KCHUNK * HID / 4)  // 6272 float4 per chunk
#define K1_SMEM (2 * KCHUNK * HID * 4)   // 200704 bytes (double buffer)

__device__ __forceinline__ void k1_issue_chunk(float* buf, int ch, int tid) {
    const float4* src = (const float4*)(g_wiT + (size_t)ch * KCHUNK * HID);
    uint32_t dsm = (uint32_t)__cvta_generic_to_shared(buf);
#pragma unroll
    for (int i = 0; i < 13; ++i) {             // ceil(6272/512)
        int idx = tid + i * K1_THREADS;
        if (idx < CHUNK_F4)
            asm volatile("cp.async.cg.shared.global [%0], [%1], 16;"
                         :: "r"(dsm + idx * 16), "l"(src + idx));
    }
    asm volatile("cp.async.commit_group;");
}

__global__ __launch_bounds__(K1_THREADS, 1) void k1_xw(const float* __restrict__ x) {
    extern __shared__ float k1smem[];
    float* buf[2] = { k1smem, k1smem + KCHUNK * HID };

    const int tid  = threadIdx.x;
    const int lane = tid & 31;
    const int wrp  = tid >> 5;
    const int rbase = blockIdx.x * RPC + wrp * RPW;

    ull p[RPW][4], tot[RPW][4];
#pragma unroll
    for (int r = 0; r < RPW; ++r)
#pragma unroll
        for (int j = 0; j < 4; ++j) { p[r][j] = 0ULL; tot[r][j] = 0ULL; }

    k1_issue_chunk(buf[0], 0, tid);

    for (int ch = 0; ch < NCHUNK; ++ch) {
        if (ch + 1 < NCHUNK) {
            k1_issue_chunk(buf[(ch + 1) & 1], ch + 1, tid);
            asm volatile("cp.async.wait_group 1;");
        } else {
            asm volatile("cp.async.wait_group 0;");
        }
        __syncthreads();                       // chunk ch visible to all

        const float* tile = buf[ch & 1];
#pragma unroll
        for (int w4 = 0; w4 < 4; ++w4) {
            const bool lv = (w4 < 3) || (lane < 2);   // 98 = 3*32 + 2
            uint32_t m[RPW];
#pragma unroll
            for (int r = 0; r < RPW; ++r) {
                const float* xr = x + (size_t)(rbase + r) * NIN + ch * KCHUNK;
                float xv = lv ? xr[w4 * 32 + lane] : 0.0f;
                m[r] = __ballot_sync(0xffffffffu, xv != 0.0f);
            }
            uint32_t u = m[0] | m[1] | m[2] | m[3];
            while (u) {
                int bit = __ffs(u) - 1;
                u &= u - 1;
                int kl = w4 * 32 + bit;
                ulonglong2 wa = *(const ulonglong2*)&tile[kl * HID + lane * 4];
                ulonglong2 wb = *(const ulonglong2*)&tile[kl * HID + 128 + lane * 4];
#pragma unroll
                for (int r = 0; r < RPW; ++r) {
                    float xf = (float)((m[r] >> bit) & 1u);
                    uint32_t xu = __float_as_uint(xf);
                    ull xd; asm("mov.b64 %0, {%1, %1};" : "=l"(xd) : "r"(xu));
                    p[r][0] = f2_fma(xd, wa.x, p[r][0]);
                    p[r][1] = f2_fma(xd, wa.y, p[r][1]);
                    p[r][2] = f2_fma(xd, wb.x, p[r][2]);
                    p[r][3] = f2_fma(xd, wb.y, p[r][3]);
                }
            }
        }

        // 98-chunk boundary: ascending combine (identical to R5)
#pragma unroll
        for (int r = 0; r < RPW; ++r)
#pragma unroll
            for (int j = 0; j < 4; ++j) {
                tot[r][j] = f2_add(tot[r][j], p[r][j]);
                p[r][j] = 0ULL;
            }
        __syncthreads();   // all warps done with buf[ch&1] before it is re-filled
    }

#pragma unroll
    for (int r = 0; r < RPW; ++r) {
        float* o = g_xw + (size_t)(rbase + r) * HID;
        *(ulonglong2*)&o[lane * 4]       = make_ulonglong2(tot[r][0], tot[r][1]);
        *(ulonglong2*)&o[128 + lane * 4] = make_ulonglong2(tot[r][2], tot[r][3]);
    }
}

// ---------------------------------------------------------------------------
// LIF elementwise update, separately rounded fp32 ops (matches reference HLO)
// ---------------------------------------------------------------------------
__device__ __forceinline__ void lif_lane(float& v, float& i, float xw, float rec,
                                         unsigned& z) {
    float vd = __fadd_rn(v, __fmul_rn(0.05f, __fadd_rn(__fsub_rn(0.0f, v), i)));
    float id = __fmul_rn(i, 0.9f);
    z = vd > 0.5f;
    v = z ? 0.0f : vd;
    i = __fadd_rn(__fadd_rn(id, xw), rec);
}

// ---------------------------------------------------------------------------
// K2: persistent LIF recurrence (R5 shape: 8 rows/CTA, 256 threads, 128 CTAs).
// Recurrent drive = split-K=8 over WrT rows selected by the PREVIOUS step's
// spike bitmask (in-order within each 32-wide word, words ascending).
// g_xw streamed with .cs so WrT stays L1-resident. Readout deferred.
// ---------------------------------------------------------------------------
__global__ __launch_bounds__(256) void k2_steps(const float* __restrict__ Wout,
                                                const float* __restrict__ bout,
                                                float* __restrict__ out) {
    __shared__ uint32_t s_hist[T_STEPS][8][8];
    __shared__ uint8_t  s_nib[8][64];
    __shared__ float    s_part[80][3];

    const int tid = threadIdx.x;
    const int q   = tid & 63;
    const int p   = tid >> 6;
    const int b0  = blockIdx.x * 8;

    float4 v[2], cu[2];
    v[0]  = make_float4(0.f, 0.f, 0.f, 0.f);
    v[1]  = v[0];
    cu[0] = v[0];
    cu[1] = v[0];

    for (int t = 0; t < T_STEPS; ++t) {
#pragma unroll
        for (int rr = 0; rr < 2; ++rr) {
            const int r = p + rr * 4;
            const float4 xwv = __ldcs(
                (const float4*)&g_xw[((size_t)(t * BATCH + b0 + r) * HID) + q * 4]);

            // recurrent drive: split-K over 8 words of 32 spikes each
            ull rec0 = 0, rec1 = 0;
            if (t > 0) {
                const uint32_t* mrow = s_hist[t - 1][r];
#pragma unroll
                for (int w8 = 0; w8 < 8; ++w8) {
                    uint32_t m = mrow[w8];
                    ull pw0 = 0, pw1 = 0;            // word partial
                    while (m) {
                        int bpos = __ffs(m) - 1;
                        m &= m - 1;
                        ulonglong2 wr =
                            *(const ulonglong2*)&g_wrT[(w8 * 32 + bpos) * HID + q * 4];
                        pw0 = f2_add(pw0, wr.x);
                        pw1 = f2_add(pw1, wr.y);
                    }
                    rec0 = f2_add(rec0, pw0);        // ascending combine
                    rec1 = f2_add(rec1, pw1);
                }
            }
            float2 ra = *(float2*)&rec0;
            float2 rb = *(float2*)&rec1;

            unsigned zx, zy, zz, zw;
            lif_lane(v[rr].x, cu[rr].x, xwv.x, ra.x, zx);
            lif_lane(v[rr].y, cu[rr].y, xwv.y, ra.y, zy);
            lif_lane(v[rr].z, cu[rr].z, xwv.z, rb.x, zz);
            lif_lane(v[rr].w, cu[rr].w, xwv.w, rb.y, zw);
            s_nib[r][q] = (uint8_t)(zx | (zy << 1) | (zz << 2) | (zw << 3));
        }

        __syncthreads();
        if (tid < 64) {
            int r = tid >> 3, w = tid & 7;
            uint32_t word = 0;
#pragma unroll
            for (int j = 0; j < 8; ++j)
                word |= (uint32_t)s_nib[r][w * 8 + j] << (4 * j);
            s_hist[t][r][w] = word;
        }
        __syncthreads();
    }

    // deferred readout (no feedback; ordering perturbs only ~1e-7 relative)
    if (tid < 240) {
        int pair = tid / 3, seg = tid - pair * 3;
        int g = pair / NL, l = pair - g * NL;
        int t0 = seg * 17;
        int t1 = (seg == 2) ? T_STEPS : t0 + 17;
        float s = 0.0f;
        for (int t = t0; t < t1; ++t) {
#pragma unroll
            for (int w8 = 0; w8 < 8; ++w8) {
                uint32_t m = s_hist[t][g][w8];
                while (m) {
                    int bpos = __ffs(m) - 1;
                    m &= m - 1;
                    s = __fadd_rn(s, Wout[l * HID + w8 * 32 + bpos]);
                }
            }
        }
        s_part[pair][seg] = s;
    }
    __syncthreads();
    if (tid < 80) {
        int g = tid / NL, l = tid - (tid / NL) * NL;
        float a = __fadd_rn(__fadd_rn(s_part[tid][0], s_part[tid][1]), s_part[tid][2]);
        float val = __fdiv_rn(__fadd_rn(a, __fmul_rn((float)T_STEPS, bout[l])),
                              (float)T_STEPS);
        out[(b0 + g) * NL + l] = val;
    }
}

// ---------------------------------------------------------------------------
extern "C" void kernel_launch(void* const* d_in, const int* in_sizes, int n_in,
                              void* d_out, int out_size) {
    const float* x    = (const float*)d_in[0];
    const float* Wi   = (const float*)d_in[1];
    const float* Wr   = (const float*)d_in[2];
    const float* Wout = (const float*)d_in[3];
    const float* bout = (const float*)d_in[4];
    float* out = (float*)d_out;

    k0_prep<<<(NIN * HID + 255) / 256, 256>>>(Wi, Wr);

    static bool attr_set = false;
    if (!attr_set) {
        cudaFuncSetAttribute(k1_xw, cudaFuncAttributeMaxDynamicSharedMemorySize,
                             K1_SMEM);
        attr_set = true;
    }
    k1_xw<<<NROWS / RPC, K1_THREADS, K1_SMEM>>>(x);

    k2_steps<<<BATCH / 8, 256>>>(Wout, bout, out);
}

// round 9
// speedup vs baseline: 1.1614x; 1.0733x over previous
#include <cuda_runtime.h>
#include <cstdint>

#define T_STEPS 50
#define BATCH   1024
#define NIN     784
#define HID     256
#define NL      10
#define NROWS   (T_STEPS * BATCH)   // 51200

// scratch (static device arrays; no runtime allocation)
__device__ float g_wiT[NIN * HID];      // WiT[k][h] = Wi[h][k]
__device__ float g_wrT[HID * HID];      // WrT[k][h] = Wr[h][k]
__device__ float g_xw[NROWS * HID];     // XW[t*B+b][h], split-K-8 rounding

typedef unsigned long long ull;

// ---------------- packed f32x2 helpers (2 independent IEEE-rn fp32 lanes) ---
__device__ __forceinline__ ull f2_add(ull a, ull b) {
    ull r; asm("add.rn.f32x2 %0, %1, %2;" : "=l"(r) : "l"(a), "l"(b)); return r;
}

// ---------------------------------------------------------------------------
// K0: build WiT and WrT
// ---------------------------------------------------------------------------
__global__ void k0_prep(const float* __restrict__ Wi, const float* __restrict__ Wr) {
    int idx = blockIdx.x * 256 + threadIdx.x;
    if (idx < NIN * HID) {
        int k = idx >> 8;
        int h = idx & 255;
        g_wiT[idx] = Wi[h * NIN + k];
    }
    if (idx < HID * HID) {
        int k = idx >> 8;
        int h = idx & 255;
        g_wrT[idx] = Wr[h * HID + k];
    }
}

// ---------------------------------------------------------------------------
// K1: XW[r][h] = split-K=8 sum over {k : x[r][k]=1} of WiT[k][h]
//   8 chunks of 98; within a chunk: in-order plain fp32 adds (products exact
//   for binary x); chunk partials combined in ascending chunk order.
// EXACT R5 inner loop (per-row sparse scan, 2x LDS.128 + 4x ADD.f32x2/visit).
// NEW vs R5: WiT chunks double-buffered via cp.async (2 x 100352 B smem) so
// staging of chunk ch+1 overlaps the scan of chunk ch.
// 512 threads = 16 warps; warp owns 4 rows; lane owns h = lane*4..+3 and
// 128+lane*4..+3 (conflict-free LDS.128).
// ---------------------------------------------------------------------------
#define K1_THREADS 512
#define RPW 4                        // rows per warp
#define RPC 64                       // rows per CTA (16 warps * 4)
#define KCHUNK 98
#define NCHUNK 8
#define CHUNK_F4 (KCHUNK * HID / 4)  // 6272 float4 per chunk
#define K1_SMEM (2 * KCHUNK * HID * 4)   // 200704 bytes (double buffer)

__device__ __forceinline__ void k1_issue_chunk(float* buf, int ch, int tid) {
    const float4* src = (const float4*)(g_wiT + (size_t)ch * KCHUNK * HID);
    uint32_t dsm = (uint32_t)__cvta_generic_to_shared(buf);
#pragma unroll
    for (int i = 0; i < 13; ++i) {             // ceil(6272/512)
        int idx = tid + i * K1_THREADS;
        if (idx < CHUNK_F4)
            asm volatile("cp.async.cg.shared.global [%0], [%1], 16;"
                         :: "r"(dsm + idx * 16), "l"(src + idx));
    }
    asm volatile("cp.async.commit_group;");
}

__global__ __launch_bounds__(K1_THREADS, 1) void k1_xw(const float* __restrict__ x) {
    extern __shared__ float k1smem[];
    float* buf[2] = { k1smem, k1smem + KCHUNK * HID };

    const int tid  = threadIdx.x;
    const int lane = tid & 31;
    const int wrp  = tid >> 5;
    const int rbase = blockIdx.x * RPC + wrp * RPW;

    ull tot[RPW][4];                 // running split-K totals
#pragma unroll
    for (int r = 0; r < RPW; ++r)
#pragma unroll
        for (int j = 0; j < 4; ++j) tot[r][j] = 0ULL;

    k1_issue_chunk(buf[0], 0, tid);

    for (int ch = 0; ch < NCHUNK; ++ch) {
        if (ch + 1 < NCHUNK) {
            k1_issue_chunk(buf[(ch + 1) & 1], ch + 1, tid);
            asm volatile("cp.async.wait_group 1;");
        } else {
            asm volatile("cp.async.wait_group 0;");
        }
        __syncthreads();                       // chunk ch visible to all

        const float* tile = buf[ch & 1];
#pragma unroll
        for (int r = 0; r < RPW; ++r) {
            const float* xr = x + (size_t)(rbase + r) * NIN + ch * KCHUNK;
            ull p0 = 0, p1 = 0, p2 = 0, p3 = 0;    // chunk partial
#pragma unroll
            for (int w4 = 0; w4 < 4; ++w4) {
                const bool lv = (w4 < 3) || (lane < 2);   // 98 = 3*32 + 2
                float xv = lv ? xr[w4 * 32 + lane] : 0.0f;
                unsigned m = __ballot_sync(0xffffffffu, xv != 0.0f);
                while (m) {
                    int kl = w4 * 32 + __ffs(m) - 1;
                    m &= m - 1;
                    ulonglong2 wa = *(const ulonglong2*)&tile[kl * HID + lane * 4];
                    ulonglong2 wb = *(const ulonglong2*)&tile[kl * HID + 128 + lane * 4];
                    p0 = f2_add(p0, wa.x);
                    p1 = f2_add(p1, wa.y);
                    p2 = f2_add(p2, wb.x);
                    p3 = f2_add(p3, wb.y);
                }
            }
            tot[r][0] = f2_add(tot[r][0], p0);   // ascending chunk combine
            tot[r][1] = f2_add(tot[r][1], p1);
            tot[r][2] = f2_add(tot[r][2], p2);
            tot[r][3] = f2_add(tot[r][3], p3);
        }
        __syncthreads();   // all warps done with buf[ch&1] before re-fill
    }

#pragma unroll
    for (int r = 0; r < RPW; ++r) {
        float* o = g_xw + (size_t)(rbase + r) * HID;
        *(ulonglong2*)&o[lane * 4]       = make_ulonglong2(tot[r][0], tot[r][1]);
        *(ulonglong2*)&o[128 + lane * 4] = make_ulonglong2(tot[r][2], tot[r][3]);
    }
}

// ---------------------------------------------------------------------------
// LIF elementwise update, separately rounded fp32 ops (matches reference HLO)
// ---------------------------------------------------------------------------
__device__ __forceinline__ void lif_lane(float& v, float& i, float xw, float rec,
                                         unsigned& z) {
    float vd = __fadd_rn(v, __fmul_rn(0.05f, __fadd_rn(__fsub_rn(0.0f, v), i)));
    float id = __fmul_rn(i, 0.9f);
    z = vd > 0.5f;
    v = z ? 0.0f : vd;
    i = __fadd_rn(__fadd_rn(id, xw), rec);
}

// ---------------------------------------------------------------------------
// K2: persistent LIF recurrence (R5 shape: 8 rows/CTA, 256 threads, 128 CTAs).
// Recurrent drive = split-K=8 over WrT rows selected by the PREVIOUS step's
// spike bitmask (in-order within each 32-wide word, words ascending).
// g_xw streamed with .cs so WrT stays L1-resident. Readout deferred.
// ---------------------------------------------------------------------------
__global__ __launch_bounds__(256) void k2_steps(const float* __restrict__ Wout,
                                                const float* __restrict__ bout,
                                                float* __restrict__ out) {
    __shared__ uint32_t s_hist[T_STEPS][8][8];
    __shared__ uint8_t  s_nib[8][64];
    __shared__ float    s_part[80][3];

    const int tid = threadIdx.x;
    const int q   = tid & 63;
    const int p   = tid >> 6;
    const int b0  = blockIdx.x * 8;

    float4 v[2], cu[2];
    v[0]  = make_float4(0.f, 0.f, 0.f, 0.f);
    v[1]  = v[0];
    cu[0] = v[0];
    cu[1] = v[0];

    for (int t = 0; t < T_STEPS; ++t) {
#pragma unroll
        for (int rr = 0; rr < 2; ++rr) {
            const int r = p + rr * 4;
            const float4 xwv = __ldcs(
                (const float4*)&g_xw[((size_t)(t * BATCH + b0 + r) * HID) + q * 4]);

            // recurrent drive: split-K over 8 words of 32 spikes each
            ull rec0 = 0, rec1 = 0;
            if (t > 0) {
                const uint32_t* mrow = s_hist[t - 1][r];
#pragma unroll
                for (int w8 = 0; w8 < 8; ++w8) {
                    uint32_t m = mrow[w8];
                    ull pw0 = 0, pw1 = 0;            // word partial
                    while (m) {
                        int bpos = __ffs(m) - 1;
                        m &= m - 1;
                        ulonglong2 wr =
                            *(const ulonglong2*)&g_wrT[(w8 * 32 + bpos) * HID + q * 4];
                        pw0 = f2_add(pw0, wr.x);
                        pw1 = f2_add(pw1, wr.y);
                    }
                    rec0 = f2_add(rec0, pw0);        // ascending combine
                    rec1 = f2_add(rec1, pw1);
                }
            }
            float2 ra = *(float2*)&rec0;
            float2 rb = *(float2*)&rec1;

            unsigned zx, zy, zz, zw;
            lif_lane(v[rr].x, cu[rr].x, xwv.x, ra.x, zx);
            lif_lane(v[rr].y, cu[rr].y, xwv.y, ra.y, zy);
            lif_lane(v[rr].z, cu[rr].z, xwv.z, rb.x, zz);
            lif_lane(v[rr].w, cu[rr].w, xwv.w, rb.y, zw);
            s_nib[r][q] = (uint8_t)(zx | (zy << 1) | (zz << 2) | (zw << 3));
        }

        __syncthreads();
        if (tid < 64) {
            int r = tid >> 3, w = tid & 7;
            uint32_t word = 0;
#pragma unroll
            for (int j = 0; j < 8; ++j)
                word |= (uint32_t)s_nib[r][w * 8 + j] << (4 * j);
            s_hist[t][r][w] = word;
        }
        __syncthreads();
    }

    // deferred readout (no feedback; ordering perturbs only ~1e-7 relative)
    if (tid < 240) {
        int pair = tid / 3, seg = tid - pair * 3;
        int g = pair / NL, l = pair - g * NL;
        int t0 = seg * 17;
        int t1 = (seg == 2) ? T_STEPS : t0 + 17;
        float s = 0.0f;
        for (int t = t0; t < t1; ++t) {
#pragma unroll
            for (int w8 = 0; w8 < 8; ++w8) {
                uint32_t m = s_hist[t][g][w8];
                while (m) {
                    int bpos = __ffs(m) - 1;
                    m &= m - 1;
                    s = __fadd_rn(s, Wout[l * HID + w8 * 32 + bpos]);
                }
            }
        }
        s_part[pair][seg] = s;
    }
    __syncthreads();
    if (tid < 80) {
        int g = tid / NL, l = tid - (tid / NL) * NL;
        float a = __fadd_rn(__fadd_rn(s_part[tid][0], s_part[tid][1]), s_part[tid][2]);
        float val = __fdiv_rn(__fadd_rn(a, __fmul_rn((float)T_STEPS, bout[l])),
                              (float)T_STEPS);
        out[(b0 + g) * NL + l] = val;
    }
}

// ---------------------------------------------------------------------------
extern "C" void kernel_launch(void* const* d_in, const int* in_sizes, int n_in,
                              void* d_out, int out_size) {
    const float* x    = (const float*)d_in[0];
    const float* Wi   = (const float*)d_in[1];
    const float* Wr   = (const float*)d_in[2];
    const float* Wout = (const float*)d_in[3];
    const float* bout = (const float*)d_in[4];
    float* out = (float*)d_out;

    k0_prep<<<(NIN * HID + 255) / 256, 256>>>(Wi, Wr);

    static bool attr_set = false;
    if (!attr_set) {
        cudaFuncSetAttribute(k1_xw, cudaFuncAttributeMaxDynamicSharedMemorySize,
                             K1_SMEM);
        attr_set = true;
    }
    k1_xw<<<NROWS / RPC, K1_THREADS, K1_SMEM>>>(x);

    k2_steps<<<BATCH / 8, 256>>>(Wout, bout, out);
}

// round 10
// speedup vs baseline: 1.4283x; 1.2298x over previous
#include <cuda_runtime.h>
#include <cstdint>

#define T_STEPS 50
#define BATCH   1024
#define NIN     784
#define HID     256
#define NL      10
#define NROWS   (T_STEPS * BATCH)   // 51200

// scratch (static device arrays; no runtime allocation)
__device__ float g_wiT[NIN * HID];      // WiT[k][h] = Wi[h][k]
__device__ float g_wrT[HID * HID];      // WrT[k][h] = Wr[h][k]
__device__ float g_xw[NROWS * HID];     // XW[t*B+b][h], split-K-8 rounding

typedef unsigned long long ull;

// ---------------- packed f32x2 helpers (2 independent IEEE-rn fp32 lanes) ---
__device__ __forceinline__ ull f2_add(ull a, ull b) {
    ull r; asm("add.rn.f32x2 %0, %1, %2;" : "=l"(r) : "l"(a), "l"(b)); return r;
}

// ---------------------------------------------------------------------------
// K0: build WiT and WrT
// ---------------------------------------------------------------------------
__global__ void k0_prep(const float* __restrict__ Wi, const float* __restrict__ Wr) {
    int idx = blockIdx.x * 256 + threadIdx.x;
    if (idx < NIN * HID) {
        int k = idx >> 8;
        int h = idx & 255;
        g_wiT[idx] = Wi[h * NIN + k];
    }
    if (idx < HID * HID) {
        int k = idx >> 8;
        int h = idx & 255;
        g_wrT[idx] = Wr[h * HID + k];
    }
}

// ---------------------------------------------------------------------------
// K1 (staging-free): XW[r][h] = split-K=8 sum over {k : x[r][k]=1} of
// WiT[k][h]; 8 chunks of 98, in-order within a chunk, chunk partials combined
// ascending — IDENTICAL add sequence to R5, only the load path changes:
// weight rows come straight from L1 via LDG.128 (no smem, no staging copies,
// no barriers). Per-chunk working set = 98 x 1KB = 100KB; 1024-thread CTAs
// cap residency at 2 CTAs/SM, both scanning the same chunk in near-lockstep,
// so the combined footprint (~200KB + evict-first x stream) fits the full
// 228KB L1 (no smem carveout). x is read with __ldcs to avoid evicting WiT.
// 32 warps; warp owns 4 rows; lane owns h = lane*4..+3 and 128+lane*4..+3.
// ---------------------------------------------------------------------------
#define K1_THREADS 1024
#define RPW 4                        // rows per warp
#define RPC 128                      // rows per CTA (32 warps * 4)
#define KCHUNK 98
#define NCHUNK 8

__global__ __launch_bounds__(K1_THREADS) void k1_xw(const float* __restrict__ x) {
    const int tid  = threadIdx.x;
    const int lane = tid & 31;
    const int wrp  = tid >> 5;
    const int rbase = blockIdx.x * RPC + wrp * RPW;

    ull tot[RPW][4];                 // running split-K totals
#pragma unroll
    for (int r = 0; r < RPW; ++r)
#pragma unroll
        for (int j = 0; j < 4; ++j) tot[r][j] = 0ULL;

    for (int ch = 0; ch < NCHUNK; ++ch) {
        const float* wch = g_wiT + (size_t)ch * KCHUNK * HID;
#pragma unroll
        for (int r = 0; r < RPW; ++r) {
            const float* xr = x + (size_t)(rbase + r) * NIN + ch * KCHUNK;
            ull p0 = 0, p1 = 0, p2 = 0, p3 = 0;    // chunk partial
#pragma unroll
            for (int w4 = 0; w4 < 4; ++w4) {
                const bool lv = (w4 < 3) || (lane < 2);   // 98 = 3*32 + 2
                float xv = lv ? __ldcs(&xr[w4 * 32 + lane]) : 0.0f;
                unsigned m = __ballot_sync(0xffffffffu, xv != 0.0f);
                while (m) {
                    int kl = w4 * 32 + __ffs(m) - 1;
                    m &= m - 1;
                    const float* wrow = wch + kl * HID;
                    ulonglong2 wa = *(const ulonglong2*)(wrow + lane * 4);
                    ulonglong2 wb = *(const ulonglong2*)(wrow + 128 + lane * 4);
                    p0 = f2_add(p0, wa.x);
                    p1 = f2_add(p1, wa.y);
                    p2 = f2_add(p2, wb.x);
                    p3 = f2_add(p3, wb.y);
                }
            }
            tot[r][0] = f2_add(tot[r][0], p0);   // ascending chunk combine
            tot[r][1] = f2_add(tot[r][1], p1);
            tot[r][2] = f2_add(tot[r][2], p2);
            tot[r][3] = f2_add(tot[r][3], p3);
        }
    }

#pragma unroll
    for (int r = 0; r < RPW; ++r) {
        float* o = g_xw + (size_t)(rbase + r) * HID;
        *(ulonglong2*)&o[lane * 4]       = make_ulonglong2(tot[r][0], tot[r][1]);
        *(ulonglong2*)&o[128 + lane * 4] = make_ulonglong2(tot[r][2], tot[r][3]);
    }
}

// ---------------------------------------------------------------------------
// LIF elementwise update, separately rounded fp32 ops (matches reference HLO)
// ---------------------------------------------------------------------------
__device__ __forceinline__ void lif_lane(float& v, float& i, float xw, float rec,
                                         unsigned& z) {
    float vd = __fadd_rn(v, __fmul_rn(0.05f, __fadd_rn(__fsub_rn(0.0f, v), i)));
    float id = __fmul_rn(i, 0.9f);
    z = vd > 0.5f;
    v = z ? 0.0f : vd;
    i = __fadd_rn(__fadd_rn(id, xw), rec);
}

// ---------------------------------------------------------------------------
// K2: persistent LIF recurrence — EXACT R5 kernel (8 rows/CTA, 256 threads,
// 128 CTAs, plain g_xw loads). Recurrent drive = split-K=8 over WrT rows
// selected by the PREVIOUS step's spike bitmask (in-order within each
// 32-wide word, words ascending). Readout deferred via recorded masks.
// ---------------------------------------------------------------------------
__global__ __launch_bounds__(256) void k2_steps(const float* __restrict__ Wout,
                                                const float* __restrict__ bout,
                                                float* __restrict__ out) {
    __shared__ uint32_t s_hist[T_STEPS][8][8];
    __shared__ uint8_t  s_nib[8][64];
    __shared__ float    s_part[80][3];

    const int tid = threadIdx.x;
    const int q   = tid & 63;
    const int p   = tid >> 6;
    const int b0  = blockIdx.x * 8;

    float4 v[2], cu[2];
    v[0]  = make_float4(0.f, 0.f, 0.f, 0.f);
    v[1]  = v[0];
    cu[0] = v[0];
    cu[1] = v[0];

    for (int t = 0; t < T_STEPS; ++t) {
#pragma unroll
        for (int rr = 0; rr < 2; ++rr) {
            const int r = p + rr * 4;
            const float4 xwv =
                *(const float4*)&g_xw[((size_t)(t * BATCH + b0 + r) * HID) + q * 4];

            // recurrent drive: split-K over 8 words of 32 spikes each
            ull rec0 = 0, rec1 = 0;
            if (t > 0) {
                const uint32_t* mrow = s_hist[t - 1][r];
#pragma unroll
                for (int w8 = 0; w8 < 8; ++w8) {
                    uint32_t m = mrow[w8];
                    ull pw0 = 0, pw1 = 0;            // word partial
                    while (m) {
                        int bpos = __ffs(m) - 1;
                        m &= m - 1;
                        ulonglong2 wr =
                            *(const ulonglong2*)&g_wrT[(w8 * 32 + bpos) * HID + q * 4];
                        pw0 = f2_add(pw0, wr.x);
                        pw1 = f2_add(pw1, wr.y);
                    }
                    rec0 = f2_add(rec0, pw0);        // ascending combine
                    rec1 = f2_add(rec1, pw1);
                }
            }
            float2 ra = *(float2*)&rec0;
            float2 rb = *(float2*)&rec1;

            unsigned zx, zy, zz, zw;
            lif_lane(v[rr].x, cu[rr].x, xwv.x, ra.x, zx);
            lif_lane(v[rr].y, cu[rr].y, xwv.y, ra.y, zy);
            lif_lane(v[rr].z, cu[rr].z, xwv.z, rb.x, zz);
            lif_lane(v[rr].w, cu[rr].w, xwv.w, rb.y, zw);
            s_nib[r][q] = (uint8_t)(zx | (zy << 1) | (zz << 2) | (zw << 3));
        }

        __syncthreads();
        if (tid < 64) {
            int r = tid >> 3, w = tid & 7;
            uint32_t word = 0;
#pragma unroll
            for (int j = 0; j < 8; ++j)
                word |= (uint32_t)s_nib[r][w * 8 + j] << (4 * j);
            s_hist[t][r][w] = word;
        }
        __syncthreads();
    }

    // deferred readout (no feedback; ordering perturbs only ~1e-7 relative)
    if (tid < 240) {
        int pair = tid / 3, seg = tid - pair * 3;
        int g = pair / NL, l = pair - g * NL;
        int t0 = seg * 17;
        int t1 = (seg == 2) ? T_STEPS : t0 + 17;
        float s = 0.0f;
        for (int t = t0; t < t1; ++t) {
#pragma unroll
            for (int w8 = 0; w8 < 8; ++w8) {
                uint32_t m = s_hist[t][g][w8];
                while (m) {
                    int bpos = __ffs(m) - 1;
                    m &= m - 1;
                    s = __fadd_rn(s, Wout[l * HID + w8 * 32 + bpos]);
                }
            }
        }
        s_part[pair][seg] = s;
    }
    __syncthreads();
    if (tid < 80) {
        int g = tid / NL, l = tid - (tid / NL) * NL;
        float a = __fadd_rn(__fadd_rn(s_part[tid][0], s_part[tid][1]), s_part[tid][2]);
        float val = __fdiv_rn(__fadd_rn(a, __fmul_rn((float)T_STEPS, bout[l])),
                              (float)T_STEPS);
        out[(b0 + g) * NL + l] = val;
    }
}

// ---------------------------------------------------------------------------
extern "C" void kernel_launch(void* const* d_in, const int* in_sizes, int n_in,
                              void* d_out, int out_size) {
    const float* x    = (const float*)d_in[0];
    const float* Wi   = (const float*)d_in[1];
    const float* Wr   = (const float*)d_in[2];
    const float* Wout = (const float*)d_in[3];
    const float* bout = (const float*)d_in[4];
    float* out = (float*)d_out;

    k0_prep<<<(NIN * HID + 255) / 256, 256>>>(Wi, Wr);

    k1_xw<<<NROWS / RPC, K1_THREADS>>>(x);

    k2_steps<<<BATCH / 8, 256>>>(Wout, bout, out);
}

// round 11
// speedup vs baseline: 1.4553x; 1.0189x over previous
#include <cuda_runtime.h>
#include <cstdint>

#define T_STEPS 50
#define BATCH   1024
#define NIN     784
#define HID     256
#define NL      10
#define NROWS   (T_STEPS * BATCH)   // 51200

// scratch (static device arrays; no runtime allocation)
__device__ float g_wiT[NIN * HID];      // WiT[k][h] = Wi[h][k]
__device__ float g_wrT[HID * HID];      // WrT[k][h] = Wr[h][k]
__device__ float g_xw[NROWS * HID];     // XW[t*B+b][h], split-K-8 rounding

typedef unsigned long long ull;

// ---------------- packed f32x2 helpers (2 independent IEEE-rn fp32 lanes) ---
__device__ __forceinline__ ull f2_add(ull a, ull b) {
    ull r; asm("add.rn.f32x2 %0, %1, %2;" : "=l"(r) : "l"(a), "l"(b)); return r;
}

// ---------------------------------------------------------------------------
// K0: build WiT and WrT
// ---------------------------------------------------------------------------
__global__ void k0_prep(const float* __restrict__ Wi, const float* __restrict__ Wr) {
    int idx = blockIdx.x * 256 + threadIdx.x;
    if (idx < NIN * HID) {
        int k = idx >> 8;
        int h = idx & 255;
        g_wiT[idx] = Wi[h * NIN + k];
    }
    if (idx < HID * HID) {
        int k = idx >> 8;
        int h = idx & 255;
        g_wrT[idx] = Wr[h * HID + k];
    }
}

// ---------------------------------------------------------------------------
// K1 (staging-free, fine-grained): XW[r][h] = split-K=8 sum over
// {k : x[r][k]=1} of WiT[k][h]; 8 chunks of 98, in-order within a chunk,
// chunk partials combined ascending — IDENTICAL add sequence to R10.
// Weight rows read straight from L1 via LDG.128 (no smem/staging/barriers);
// x read with __ldcs (evict-first) so the x stream doesn't evict WiT.
// CHANGE vs R10: RPW 4 -> 2, so each CTA covers 64 rows (800 CTAs). With
// 2 CTAs/SM (296 slots), 800/296 = 2.70 -> makespan 3 short waves (1.5x
// ideal-wave time) instead of 400/296 = 1.35 -> 2 long waves (2.0x): the
// uniform-duration wave-quantization tail drops from 48% to 11%.
// 32 warps; warp owns 2 rows; lane owns h = lane*4..+3 and 128+lane*4..+3.
// ---------------------------------------------------------------------------
#define K1_THREADS 1024
#define RPW 2                        // rows per warp
#define RPC 64                       // rows per CTA (32 warps * 2)
#define KCHUNK 98
#define NCHUNK 8

__global__ __launch_bounds__(K1_THREADS) void k1_xw(const float* __restrict__ x) {
    const int tid  = threadIdx.x;
    const int lane = tid & 31;
    const int wrp  = tid >> 5;
    const int rbase = blockIdx.x * RPC + wrp * RPW;

    ull tot[RPW][4];                 // running split-K totals
#pragma unroll
    for (int r = 0; r < RPW; ++r)
#pragma unroll
        for (int j = 0; j < 4; ++j) tot[r][j] = 0ULL;

    for (int ch = 0; ch < NCHUNK; ++ch) {
        const float* wch = g_wiT + (size_t)ch * KCHUNK * HID;
#pragma unroll
        for (int r = 0; r < RPW; ++r) {
            const float* xr = x + (size_t)(rbase + r) * NIN + ch * KCHUNK;
            ull p0 = 0, p1 = 0, p2 = 0, p3 = 0;    // chunk partial
#pragma unroll
            for (int w4 = 0; w4 < 4; ++w4) {
                const bool lv = (w4 < 3) || (lane < 2);   // 98 = 3*32 + 2
                float xv = lv ? __ldcs(&xr[w4 * 32 + lane]) : 0.0f;
                unsigned m = __ballot_sync(0xffffffffu, xv != 0.0f);
                while (m) {
                    int kl = w4 * 32 + __ffs(m) - 1;
                    m &= m - 1;
                    const float* wrow = wch + kl * HID;
                    ulonglong2 wa = *(const ulonglong2*)(wrow + lane * 4);
                    ulonglong2 wb = *(const ulonglong2*)(wrow + 128 + lane * 4);
                    p0 = f2_add(p0, wa.x);
                    p1 = f2_add(p1, wa.y);
                    p2 = f2_add(p2, wb.x);
                    p3 = f2_add(p3, wb.y);
                }
            }
            tot[r][0] = f2_add(tot[r][0], p0);   // ascending chunk combine
            tot[r][1] = f2_add(tot[r][1], p1);
            tot[r][2] = f2_add(tot[r][2], p2);
            tot[r][3] = f2_add(tot[r][3], p3);
        }
    }

#pragma unroll
    for (int r = 0; r < RPW; ++r) {
        float* o = g_xw + (size_t)(rbase + r) * HID;
        *(ulonglong2*)&o[lane * 4]       = make_ulonglong2(tot[r][0], tot[r][1]);
        *(ulonglong2*)&o[128 + lane * 4] = make_ulonglong2(tot[r][2], tot[r][3]);
    }
}

// ---------------------------------------------------------------------------
// LIF elementwise update, separately rounded fp32 ops (matches reference HLO)
// ---------------------------------------------------------------------------
__device__ __forceinline__ void lif_lane(float& v, float& i, float xw, float rec,
                                         unsigned& z) {
    float vd = __fadd_rn(v, __fmul_rn(0.05f, __fadd_rn(__fsub_rn(0.0f, v), i)));
    float id = __fmul_rn(i, 0.9f);
    z = vd > 0.5f;
    v = z ? 0.0f : vd;
    i = __fadd_rn(__fadd_rn(id, xw), rec);
}

// ---------------------------------------------------------------------------
// K2: persistent LIF recurrence (R5/R10 shape: 8 rows/CTA, 256 threads,
// 128 CTAs). Recurrent drive = split-K=8 over WrT rows selected by the
// PREVIOUS step's spike bitmask (in-order within each 32-wide word, words
// ascending). NEW: g_xw loads are software-pipelined — the float4 for step
// t+1 is issued at the top of step t, hiding its DRAM/L2 latency behind the
// WrT gather + the two barriers. Readout deferred via recorded masks.
// ---------------------------------------------------------------------------
__global__ __launch_bounds__(256) void k2_steps(const float* __restrict__ Wout,
                                                const float* __restrict__ bout,
                                                float* __restrict__ out) {
    __shared__ uint32_t s_hist[T_STEPS][8][8];
    __shared__ uint8_t  s_nib[8][64];
    __shared__ float    s_part[80][3];

    const int tid = threadIdx.x;
    const int q   = tid & 63;
    const int p   = tid >> 6;
    const int b0  = blockIdx.x * 8;

    float4 v[2], cu[2], xw_cur[2];
    v[0]  = make_float4(0.f, 0.f, 0.f, 0.f);
    v[1]  = v[0];
    cu[0] = v[0];
    cu[1] = v[0];

    // preload step-0 drives
#pragma unroll
    for (int rr = 0; rr < 2; ++rr) {
        const int r = p + rr * 4;
        xw_cur[rr] = *(const float4*)&g_xw[((size_t)(0 * BATCH + b0 + r) * HID) + q * 4];
    }

    for (int t = 0; t < T_STEPS; ++t) {
        float4 xw_next[2];
#pragma unroll
        for (int rr = 0; rr < 2; ++rr) {
            const int r = p + rr * 4;
            const float4 xwv = xw_cur[rr];
            // issue next step's load now; consumed after 2 barriers -> hidden
            if (t + 1 < T_STEPS)
                xw_next[rr] = *(const float4*)
                    &g_xw[((size_t)((t + 1) * BATCH + b0 + r) * HID) + q * 4];

            // recurrent drive: split-K over 8 words of 32 spikes each
            ull rec0 = 0, rec1 = 0;
            if (t > 0) {
                const uint32_t* mrow = s_hist[t - 1][r];
#pragma unroll
                for (int w8 = 0; w8 < 8; ++w8) {
                    uint32_t m = mrow[w8];
                    ull pw0 = 0, pw1 = 0;            // word partial
                    while (m) {
                        int bpos = __ffs(m) - 1;
                        m &= m - 1;
                        ulonglong2 wr =
                            *(const ulonglong2*)&g_wrT[(w8 * 32 + bpos) * HID + q * 4];
                        pw0 = f2_add(pw0, wr.x);
                        pw1 = f2_add(pw1, wr.y);
                    }
                    rec0 = f2_add(rec0, pw0);        // ascending combine
                    rec1 = f2_add(rec1, pw1);
                }
            }
            float2 ra = *(float2*)&rec0;
            float2 rb = *(float2*)&rec1;

            unsigned zx, zy, zz, zw;
            lif_lane(v[rr].x, cu[rr].x, xwv.x, ra.x, zx);
            lif_lane(v[rr].y, cu[rr].y, xwv.y, ra.y, zy);
            lif_lane(v[rr].z, cu[rr].z, xwv.z, rb.x, zz);
            lif_lane(v[rr].w, cu[rr].w, xwv.w, rb.y, zw);
            s_nib[r][q] = (uint8_t)(zx | (zy << 1) | (zz << 2) | (zw << 3));
        }
        xw_cur[0] = xw_next[0];
        xw_cur[1] = xw_next[1];

        __syncthreads();
        if (tid < 64) {
            int r = tid >> 3, w = tid & 7;
            uint32_t word = 0;
#pragma unroll
            for (int j = 0; j < 8; ++j)
                word |= (uint32_t)s_nib[r][w * 8 + j] << (4 * j);
            s_hist[t][r][w] = word;
        }
        __syncthreads();
    }

    // deferred readout (no feedback; ordering perturbs only ~1e-7 relative)
    if (tid < 240) {
        int pair = tid / 3, seg = tid - pair * 3;
        int g = pair / NL, l = pair - g * NL;
        int t0 = seg * 17;
        int t1 = (seg == 2) ? T_STEPS : t0 + 17;
        float s = 0.0f;
        for (int t = t0; t < t1; ++t) {
#pragma unroll
            for (int w8 = 0; w8 < 8; ++w8) {
                uint32_t m = s_hist[t][g][w8];
                while (m) {
                    int bpos = __ffs(m) - 1;
                    m &= m - 1;
                    s = __fadd_rn(s, Wout[l * HID + w8 * 32 + bpos]);
                }
            }
        }
        s_part[pair][seg] = s;
    }
    __syncthreads();
    if (tid < 80) {
        int g = tid / NL, l = tid - (tid / NL) * NL;
        float a = __fadd_rn(__fadd_rn(s_part[tid][0], s_part[tid][1]), s_part[tid][2]);
        float val = __fdiv_rn(__fadd_rn(a, __fmul_rn((float)T_STEPS, bout[l])),
                              (float)T_STEPS);
        out[(b0 + g) * NL + l] = val;
    }
}

// ---------------------------------------------------------------------------
extern "C" void kernel_launch(void* const* d_in, const int* in_sizes, int n_in,
                              void* d_out, int out_size) {
    const float* x    = (const float*)d_in[0];
    const float* Wi   = (const float*)d_in[1];
    const float* Wr   = (const float*)d_in[2];
    const float* Wout = (const float*)d_in[3];
    const float* bout = (const float*)d_in[4];
    float* out = (float*)d_out;

    k0_prep<<<(NIN * HID + 255) / 256, 256>>>(Wi, Wr);

    k1_xw<<<NROWS / RPC, K1_THREADS>>>(x);

    k2_steps<<<BATCH / 8, 256>>>(Wout, bout, out);
}